// round 7
// baseline (speedup 1.0000x reference)
#include <cuda_runtime.h>
#include <cuda_fp16.h>
#include <cuda_bf16.h>

#define N_VERTS 100000
#define N_TETS  200000
#define BATCH   64
#define ROWS    (3 * N_VERTS)      // 300000

#define DET_BLOCKS 1184            // 8 CTAs/SM on 148 SMs
#define DET_THREADS 256

// batch permutation inside g_xTh: column j holds real batch sigma(j);
// sigma(t) = ((t&7)<<3)|(t>>3), self-inverse.
__device__ __forceinline__ int sigma6(int t) { return ((t & 7) << 3) | (t >> 3); }

__device__ __half g_xTh[(size_t)ROWS * BATCH];        // 38.4 MB fp16 transposed x
__device__ float  g_partial[DET_BLOCKS * BATCH];
__device__ float  g_invscale[BATCH];                  // indexed by REAL batch
__device__ unsigned g_counter;                        // zero-init, self-resetting

// ---------------------------------------------------------------------------
// Transpose x[64][300000] -> xTh[300000][64] (fp16, batch-permuted by sigma).
// Conflict-free smem: tile4[64][33] (row stride 132 floats == 4 mod 32 banks).
// Fill:  warp w, iter j: batch b=8j+w, LDG.128 of rows 4tx..4tx+3 -> STS.128.
// Drain: thread (g=tid&7, rr): 8 scalar LDS tile_f[8k+g][rr] (banks 4g+rr+32k
//        -> all distinct) -> 8 halves -> STG.128 at column octet g.
// ---------------------------------------------------------------------------
__global__ void __launch_bounds__(256)
k_transpose(const float* __restrict__ x)
{
    __shared__ float4 tile4[64][33];
    const float* tile_f = (const float*)tile4;        // tile_f[b*132 + r]
    const int row0 = blockIdx.x * 128;

    // ---- fill ----
    const int tx = threadIdx.x & 31;                  // row quad: rows 4tx..4tx+3
    const int w  = threadIdx.x >> 5;                  // warp id 0..7
    const int r4 = row0 + 4 * tx;
    if (r4 < ROWS) {                                  // ROWS%4==0 -> quad fully valid
        #pragma unroll
        for (int j = 0; j < 8; j++) {
            const int b = j * 8 + w;
            tile4[b][tx] = *(const float4*)(x + (size_t)b * ROWS + r4);
        }
    }
    __syncthreads();

    // ---- drain ----
    const int g   = threadIdx.x & 7;                  // column octet
    const int rr0 = threadIdx.x >> 3;                 // 0..31
    #pragma unroll
    for (int p = 0; p < 4; p++) {
        const int rr  = rr0 + 32 * p;
        const int row = row0 + rr;
        if (row < ROWS) {
            __half h[8];
            #pragma unroll
            for (int k = 0; k < 8; k++)
                h[k] = __float2half_rn(tile_f[(8*k + g) * 132 + rr]);
            ((uint4*)(g_xTh + (size_t)row * 64))[g] = *(const uint4*)h;
        }
    }
}

// ---------------------------------------------------------------------------
// fp16 row-group load: 4 columns (8 bytes) -> float4
// ---------------------------------------------------------------------------
__device__ __forceinline__ float4 ldh4(const __half* p)
{
    uint2 u = __ldg((const uint2*)p);
    float2 f0 = __half22float2(*(const __half2*)&u.x);
    float2 f1 = __half22float2(*(const __half2*)&u.y);
    return make_float4(f0.x, f0.y, f1.x, f1.y);
}

// ---------------------------------------------------------------------------
// Det kernel: each warp handles 2 tets x 64 columns per iteration.
// lane = (tetHalf = lane>>4, colGroup bg = lane&15); each lane computes |det|
// for 4 columns via 9 coalesced 8B loads. fp32 accumulation.
// Last block (fenced atomic ticket) reduces partials -> g_invscale (un-permuted).
// ---------------------------------------------------------------------------
__global__ void __launch_bounds__(DET_THREADS)
k_det(const int* __restrict__ M)
{
    __shared__ float sSum[8][64];
    __shared__ float sQ[4][64];
    __shared__ unsigned sTicket;

    const int wid  = threadIdx.x >> 5;
    const int lane = threadIdx.x & 31;
    const int half = lane >> 4;
    const int bg   = lane & 15;

    float acc0 = 0.f, acc1 = 0.f, acc2 = 0.f, acc3 = 0.f;

    #pragma unroll 2
    for (int base = blockIdx.x * 16; base < N_TETS; base += DET_BLOCKS * 16) {
        const int t  = base + wid * 2 + half;
        const int i0 = __ldg(M + 3 * t + 0);
        const int i1 = __ldg(M + 3 * t + 1);
        const int i2 = __ldg(M + 3 * t + 2);

        const __half* pa = g_xTh + (size_t)(3 * i0) * 64 + bg * 4;
        const __half* pb = g_xTh + (size_t)(3 * i1) * 64 + bg * 4;
        const __half* pc = g_xTh + (size_t)(3 * i2) * 64 + bg * 4;

        float4 ax = ldh4(pa), ay = ldh4(pa + 64), az = ldh4(pa + 128);
        float4 bx = ldh4(pb), by = ldh4(pb + 64), bz = ldh4(pb + 128);
        float4 cx = ldh4(pc), cy = ldh4(pc + 64), cz = ldh4(pc + 128);

        acc0 += fabsf(ax.x * (by.x * cz.x - bz.x * cy.x)
                    - ay.x * (bx.x * cz.x - bz.x * cx.x)
                    + az.x * (bx.x * cy.x - by.x * cx.x));
        acc1 += fabsf(ax.y * (by.y * cz.y - bz.y * cy.y)
                    - ay.y * (bx.y * cz.y - bz.y * cx.y)
                    + az.y * (bx.y * cy.y - by.y * cx.y));
        acc2 += fabsf(ax.z * (by.z * cz.z - bz.z * cy.z)
                    - ay.z * (bx.z * cz.z - bz.z * cx.z)
                    + az.z * (bx.z * cy.z - by.z * cx.z));
        acc3 += fabsf(ax.w * (by.w * cz.w - bz.w * cy.w)
                    - ay.w * (bx.w * cz.w - bz.w * cx.w)
                    + az.w * (bx.w * cy.w - by.w * cx.w));
    }

    acc0 += __shfl_down_sync(0xffffffffu, acc0, 16);
    acc1 += __shfl_down_sync(0xffffffffu, acc1, 16);
    acc2 += __shfl_down_sync(0xffffffffu, acc2, 16);
    acc3 += __shfl_down_sync(0xffffffffu, acc3, 16);
    if (lane < 16)
        ((float4*)sSum[wid])[bg] = make_float4(acc0, acc1, acc2, acc3);
    __syncthreads();

    if (threadIdx.x < 64) {
        float s = 0.f;
        #pragma unroll
        for (int w = 0; w < 8; w++) s += sSum[w][threadIdx.x];
        g_partial[blockIdx.x * 64 + threadIdx.x] = s;
    }
    __syncthreads();

    if (threadIdx.x == 0) {
        __threadfence();
        sTicket = atomicAdd(&g_counter, 1u);
    }
    __syncthreads();

    if (sTicket == DET_BLOCKS - 1) {           // last block finishes
        __threadfence();                       // acquire partials
        {
            const int c = threadIdx.x & 63;    // column
            const int q = threadIdx.x >> 6;    // quarter 0..3
            const volatile float* p = g_partial;
            float s = 0.f;
            const int beg = q * (DET_BLOCKS / 4), end = beg + DET_BLOCKS / 4;
            for (int blk = beg; blk < end; blk++)
                s += p[blk * 64 + c];
            sQ[q][c] = s;
        }
        __syncthreads();
        if (threadIdx.x < 64) {
            float s = ((sQ[0][threadIdx.x] + sQ[1][threadIdx.x])
                     +  sQ[2][threadIdx.x]) + sQ[3][threadIdx.x];
            g_invscale[sigma6(threadIdx.x)] = 1.0f / cbrtf(s / 6.0f);  // un-permute
        }
        if (threadIdx.x == 0)
            g_counter = 0;                     // reset for next graph replay
    }
}

// ---------------------------------------------------------------------------
// out[b][i] = x[b][i] * invscale[b]; batch via blockIdx.y.
// ---------------------------------------------------------------------------
#define N4_PER_BATCH (ROWS / 4)          // 75000

__global__ void __launch_bounds__(256)
k_out(const float4* __restrict__ x4, float4* __restrict__ out4)
{
    const int i = blockIdx.x * 256 + threadIdx.x;
    if (i < N4_PER_BATCH) {
        const int b = blockIdx.y;
        const float s = g_invscale[b];
        const size_t idx = (size_t)b * N4_PER_BATCH + i;
        float4 v = __ldcs(x4 + idx);
        v.x *= s; v.y *= s; v.z *= s; v.w *= s;
        __stcs(out4 + idx, v);
    }
}

// ---------------------------------------------------------------------------
extern "C" void kernel_launch(void* const* d_in, const int* in_sizes, int n_in,
                              void* d_out, int out_size)
{
    // x: 19,200,000 float32 ; M: 600,000 int32 — select by element count.
    const float* x;
    const int*   M;
    if (in_sizes[0] == 19200000) { x = (const float*)d_in[0]; M = (const int*)d_in[1]; }
    else                         { x = (const float*)d_in[1]; M = (const int*)d_in[0]; }
    float* o = (float*)d_out;

    k_transpose<<<(ROWS + 127) / 128, 256>>>(x);
    k_det<<<DET_BLOCKS, DET_THREADS>>>(M);
    dim3 og((N4_PER_BATCH + 255) / 256, BATCH);
    k_out<<<og, 256>>>((const float4*)x, (float4*)o);
}

// round 8
// speedup vs baseline: 1.0857x; 1.0857x over previous
#include <cuda_runtime.h>
#include <cuda_fp16.h>
#include <cuda_bf16.h>

#define N_VERTS 100000
#define N_TETS  200000
#define BATCH   64
#define ROWS    (3 * N_VERTS)      // 300000

#define DET_BLOCKS 1184            // 8 CTAs/SM on 148 SMs
#define DET_THREADS 256

// batch permutation inside g_xTh: column j holds real batch sigma(j);
// sigma(t) = ((t&7)<<3)|(t>>3), self-inverse.
__device__ __forceinline__ int sigma6(int t) { return ((t & 7) << 3) | (t >> 3); }

__device__ __half g_xTh[(size_t)ROWS * BATCH];        // 38.4 MB fp16 transposed x
__device__ float  g_partial[DET_BLOCKS * BATCH];
__device__ float  g_invscale[BATCH];                  // indexed by REAL batch
__device__ unsigned g_counter;                        // zero-init, self-resetting

// ---------------------------------------------------------------------------
// Transpose x[64][300000] -> xTh[300000][64] (fp16, batch-permuted by sigma).
// 512 threads (full occupancy: 4 CTAs/SM x 512 = 2048 thr, 4 x 34KB smem).
// Conflict-free smem: tile4[64][33] f4 (row stride 132 floats == 4 mod 32).
// Fill:  warp w (0..15), iter j: batch b=16j+w, LDG.128 of rows 4tx..4tx+3
//        -> STS.128 (8-lane phase covers 128B of banks).
// Drain: thread (g=tid&7, rr): 8 scalar LDS tile_f[(8k+g)*132 + rr], bank =
//        (4g+rr) mod 32, all 32 lanes distinct -> 8 halves -> one STG.128.
// Column octet g holds batches {8k+g} -> permutation sigma, undone in k_det.
// ---------------------------------------------------------------------------
__global__ void __launch_bounds__(512)
k_transpose(const float* __restrict__ x)
{
    __shared__ float4 tile4[64][33];
    const float* tile_f = (const float*)tile4;        // tile_f[b*132 + r]
    const int row0 = blockIdx.x * 128;

    // ---- fill ----
    const int tx = threadIdx.x & 31;                  // row quad: rows 4tx..4tx+3
    const int w  = threadIdx.x >> 5;                  // warp id 0..15
    const int r4 = row0 + 4 * tx;
    if (r4 < ROWS) {                                  // ROWS%4==0 -> quad fully valid
        #pragma unroll
        for (int j = 0; j < 4; j++) {
            const int b = j * 16 + w;
            tile4[b][tx] = *(const float4*)(x + (size_t)b * ROWS + r4);
        }
    }
    __syncthreads();

    // ---- drain ----
    const int g   = threadIdx.x & 7;                  // column octet
    const int rr0 = threadIdx.x >> 3;                 // 0..63
    #pragma unroll
    for (int p = 0; p < 2; p++) {
        const int rr  = rr0 + 64 * p;
        const int row = row0 + rr;
        if (row < ROWS) {
            __half h[8];
            #pragma unroll
            for (int k = 0; k < 8; k++)
                h[k] = __float2half_rn(tile_f[(8*k + g) * 132 + rr]);
            ((uint4*)(g_xTh + (size_t)row * 64))[g] = *(const uint4*)h;
        }
    }
}

// ---------------------------------------------------------------------------
// fp16 row-group load: 4 columns (8 bytes) -> float4
// ---------------------------------------------------------------------------
__device__ __forceinline__ float4 ldh4(const __half* p)
{
    uint2 u = __ldg((const uint2*)p);
    float2 f0 = __half22float2(*(const __half2*)&u.x);
    float2 f1 = __half22float2(*(const __half2*)&u.y);
    return make_float4(f0.x, f0.y, f1.x, f1.y);
}

// ---------------------------------------------------------------------------
// Det kernel: each warp handles 2 tets x 64 columns per iteration.
// lane = (tetHalf = lane>>4, colGroup bg = lane&15); each lane computes |det|
// for 4 columns via 9 coalesced 8B loads. fp32 accumulation.
// Last block (fenced atomic ticket) reduces partials -> g_invscale (un-permuted).
// ---------------------------------------------------------------------------
__global__ void __launch_bounds__(DET_THREADS)
k_det(const int* __restrict__ M)
{
    __shared__ float sSum[8][64];
    __shared__ float sQ[4][64];
    __shared__ unsigned sTicket;

    const int wid  = threadIdx.x >> 5;
    const int lane = threadIdx.x & 31;
    const int half = lane >> 4;
    const int bg   = lane & 15;

    float acc0 = 0.f, acc1 = 0.f, acc2 = 0.f, acc3 = 0.f;

    #pragma unroll 2
    for (int base = blockIdx.x * 16; base < N_TETS; base += DET_BLOCKS * 16) {
        const int t  = base + wid * 2 + half;
        const int i0 = __ldg(M + 3 * t + 0);
        const int i1 = __ldg(M + 3 * t + 1);
        const int i2 = __ldg(M + 3 * t + 2);

        const __half* pa = g_xTh + (size_t)(3 * i0) * 64 + bg * 4;
        const __half* pb = g_xTh + (size_t)(3 * i1) * 64 + bg * 4;
        const __half* pc = g_xTh + (size_t)(3 * i2) * 64 + bg * 4;

        float4 ax = ldh4(pa), ay = ldh4(pa + 64), az = ldh4(pa + 128);
        float4 bx = ldh4(pb), by = ldh4(pb + 64), bz = ldh4(pb + 128);
        float4 cx = ldh4(pc), cy = ldh4(pc + 64), cz = ldh4(pc + 128);

        acc0 += fabsf(ax.x * (by.x * cz.x - bz.x * cy.x)
                    - ay.x * (bx.x * cz.x - bz.x * cx.x)
                    + az.x * (bx.x * cy.x - by.x * cx.x));
        acc1 += fabsf(ax.y * (by.y * cz.y - bz.y * cy.y)
                    - ay.y * (bx.y * cz.y - bz.y * cx.y)
                    + az.y * (bx.y * cy.y - by.y * cx.y));
        acc2 += fabsf(ax.z * (by.z * cz.z - bz.z * cy.z)
                    - ay.z * (bx.z * cz.z - bz.z * cx.z)
                    + az.z * (bx.z * cy.z - by.z * cx.z));
        acc3 += fabsf(ax.w * (by.w * cz.w - bz.w * cy.w)
                    - ay.w * (bx.w * cz.w - bz.w * cx.w)
                    + az.w * (bx.w * cy.w - by.w * cx.w));
    }

    acc0 += __shfl_down_sync(0xffffffffu, acc0, 16);
    acc1 += __shfl_down_sync(0xffffffffu, acc1, 16);
    acc2 += __shfl_down_sync(0xffffffffu, acc2, 16);
    acc3 += __shfl_down_sync(0xffffffffu, acc3, 16);
    if (lane < 16)
        ((float4*)sSum[wid])[bg] = make_float4(acc0, acc1, acc2, acc3);
    __syncthreads();

    if (threadIdx.x < 64) {
        float s = 0.f;
        #pragma unroll
        for (int w = 0; w < 8; w++) s += sSum[w][threadIdx.x];
        g_partial[blockIdx.x * 64 + threadIdx.x] = s;
    }
    __syncthreads();

    if (threadIdx.x == 0) {
        __threadfence();
        sTicket = atomicAdd(&g_counter, 1u);
    }
    __syncthreads();

    if (sTicket == DET_BLOCKS - 1) {           // last block finishes
        __threadfence();                       // acquire partials
        {
            const int c = threadIdx.x & 63;    // column
            const int q = threadIdx.x >> 6;    // quarter 0..3
            const volatile float* p = g_partial;
            float s = 0.f;
            const int beg = q * (DET_BLOCKS / 4), end = beg + DET_BLOCKS / 4;
            for (int blk = beg; blk < end; blk++)
                s += p[blk * 64 + c];
            sQ[q][c] = s;
        }
        __syncthreads();
        if (threadIdx.x < 64) {
            float s = ((sQ[0][threadIdx.x] + sQ[1][threadIdx.x])
                     +  sQ[2][threadIdx.x]) + sQ[3][threadIdx.x];
            g_invscale[sigma6(threadIdx.x)] = 1.0f / cbrtf(s / 6.0f);  // un-permute
        }
        if (threadIdx.x == 0)
            g_counter = 0;                     // reset for next graph replay
    }
}

// ---------------------------------------------------------------------------
// out[b][i] = x[b][i] * invscale[b]; batch via blockIdx.y.
// ---------------------------------------------------------------------------
#define N4_PER_BATCH (ROWS / 4)          // 75000

__global__ void __launch_bounds__(256)
k_out(const float4* __restrict__ x4, float4* __restrict__ out4)
{
    const int i = blockIdx.x * 256 + threadIdx.x;
    if (i < N4_PER_BATCH) {
        const int b = blockIdx.y;
        const float s = g_invscale[b];
        const size_t idx = (size_t)b * N4_PER_BATCH + i;
        float4 v = __ldcs(x4 + idx);
        v.x *= s; v.y *= s; v.z *= s; v.w *= s;
        __stcs(out4 + idx, v);
    }
}

// ---------------------------------------------------------------------------
extern "C" void kernel_launch(void* const* d_in, const int* in_sizes, int n_in,
                              void* d_out, int out_size)
{
    // x: 19,200,000 float32 ; M: 600,000 int32 — select by element count.
    const float* x;
    const int*   M;
    if (in_sizes[0] == 19200000) { x = (const float*)d_in[0]; M = (const int*)d_in[1]; }
    else                         { x = (const float*)d_in[1]; M = (const int*)d_in[0]; }
    float* o = (float*)d_out;

    k_transpose<<<(ROWS + 127) / 128, 512>>>(x);
    k_det<<<DET_BLOCKS, DET_THREADS>>>(M);
    dim3 og((N4_PER_BATCH + 255) / 256, BATCH);
    k_out<<<og, 256>>>((const float4*)x, (float4*)o);
}

// round 10
// speedup vs baseline: 1.1991x; 1.1044x over previous
#include <cuda_runtime.h>
#include <cuda_fp16.h>
#include <cuda_bf16.h>

#define N_VERTS 100000
#define N_TETS  200000
#define BATCH   64
#define ROWS    (3 * N_VERTS)      // 300000

#define DET_BLOCKS 1184            // 8 CTAs/SM on 148 SMs
#define DET_THREADS 256

// batch permutation inside g_xTh: column j holds real batch sigma(j);
// sigma(t) = ((t&7)<<3)|(t>>3), self-inverse.
__device__ __forceinline__ int sigma6(int t) { return ((t & 7) << 3) | (t >> 3); }

__device__ __half g_xTh[(size_t)ROWS * BATCH];        // 38.4 MB fp16 transposed x
__device__ float  g_partial[DET_BLOCKS * BATCH];
__device__ float  g_invscale[BATCH];                  // indexed by REAL batch
__device__ unsigned g_counter;                        // zero-init, self-resetting

// ---------------------------------------------------------------------------
// Transpose x[64][300000] -> xTh[300000][64] (fp16, batch-permuted by sigma).
// x is read exactly once in the pipeline -> __ldcs (evict-first), keeping L2
// for xTh which det and outT both consume.
// Drain detail: thread-octet g gathers smem columns {8k+g} and stores them as
// CONTIGUOUS halves 8g+k of the row => stored column j=8g+k holds real batch
// 8k+g = sigma(j).
// ---------------------------------------------------------------------------
__global__ void __launch_bounds__(512)
k_transpose(const float* __restrict__ x)
{
    __shared__ float4 tile4[64][33];
    const float* tile_f = (const float*)tile4;        // tile_f[b*132 + r]
    const int row0 = blockIdx.x * 128;

    // ---- fill: warp w, iter j: batch b=16j+w, LDG.128 of rows 4tx..4tx+3 ----
    const int tx = threadIdx.x & 31;
    const int w  = threadIdx.x >> 5;                  // 0..15
    const int r4 = row0 + 4 * tx;
    if (r4 < ROWS) {                                  // ROWS%4==0 -> quad fully valid
        #pragma unroll
        for (int j = 0; j < 4; j++) {
            const int b = j * 16 + w;
            float4 v;
            const float* p = x + (size_t)b * ROWS + r4;
            v.x = __ldcs(p + 0); v.y = __ldcs(p + 1);
            v.z = __ldcs(p + 2); v.w = __ldcs(p + 3);
            tile4[b][tx] = v;
        }
    }
    __syncthreads();

    // ---- drain: thread (g, rr): 8 LDS (banks 4g+rr, distinct) -> STG.128 ----
    const int g   = threadIdx.x & 7;
    const int rr0 = threadIdx.x >> 3;                 // 0..63
    #pragma unroll
    for (int p = 0; p < 2; p++) {
        const int rr  = rr0 + 64 * p;
        const int row = row0 + rr;
        if (row < ROWS) {
            __half h[8];
            #pragma unroll
            for (int k = 0; k < 8; k++)
                h[k] = __float2half_rn(tile_f[(8*k + g) * 132 + rr]);
            ((uint4*)(g_xTh + (size_t)row * 64))[g] = *(const uint4*)h;
        }
    }
}

// ---------------------------------------------------------------------------
// fp16 row-group load: 4 columns (8 bytes) -> float4
// ---------------------------------------------------------------------------
__device__ __forceinline__ float4 ldh4(const __half* p)
{
    uint2 u = __ldg((const uint2*)p);
    float2 f0 = __half22float2(*(const __half2*)&u.x);
    float2 f1 = __half22float2(*(const __half2*)&u.y);
    return make_float4(f0.x, f0.y, f1.x, f1.y);
}

// ---------------------------------------------------------------------------
// Det kernel: each warp handles 2 tets x 64 columns per iteration.
// Last block (fenced atomic ticket) reduces partials -> g_invscale (un-permuted).
// ---------------------------------------------------------------------------
__global__ void __launch_bounds__(DET_THREADS)
k_det(const int* __restrict__ M)
{
    __shared__ float sSum[8][64];
    __shared__ float sQ[4][64];
    __shared__ unsigned sTicket;

    const int wid  = threadIdx.x >> 5;
    const int lane = threadIdx.x & 31;
    const int half = lane >> 4;
    const int bg   = lane & 15;

    float acc0 = 0.f, acc1 = 0.f, acc2 = 0.f, acc3 = 0.f;

    #pragma unroll 2
    for (int base = blockIdx.x * 16; base < N_TETS; base += DET_BLOCKS * 16) {
        const int t  = base + wid * 2 + half;
        const int i0 = __ldg(M + 3 * t + 0);
        const int i1 = __ldg(M + 3 * t + 1);
        const int i2 = __ldg(M + 3 * t + 2);

        const __half* pa = g_xTh + (size_t)(3 * i0) * 64 + bg * 4;
        const __half* pb = g_xTh + (size_t)(3 * i1) * 64 + bg * 4;
        const __half* pc = g_xTh + (size_t)(3 * i2) * 64 + bg * 4;

        float4 ax = ldh4(pa), ay = ldh4(pa + 64), az = ldh4(pa + 128);
        float4 bx = ldh4(pb), by = ldh4(pb + 64), bz = ldh4(pb + 128);
        float4 cx = ldh4(pc), cy = ldh4(pc + 64), cz = ldh4(pc + 128);

        acc0 += fabsf(ax.x * (by.x * cz.x - bz.x * cy.x)
                    - ay.x * (bx.x * cz.x - bz.x * cx.x)
                    + az.x * (bx.x * cy.x - by.x * cx.x));
        acc1 += fabsf(ax.y * (by.y * cz.y - bz.y * cy.y)
                    - ay.y * (bx.y * cz.y - bz.y * cx.y)
                    + az.y * (bx.y * cy.y - by.y * cx.y));
        acc2 += fabsf(ax.z * (by.z * cz.z - bz.z * cy.z)
                    - ay.z * (bx.z * cz.z - bz.z * cx.z)
                    + az.z * (bx.z * cy.z - by.z * cx.z));
        acc3 += fabsf(ax.w * (by.w * cz.w - bz.w * cy.w)
                    - ay.w * (bx.w * cz.w - bz.w * cx.w)
                    + az.w * (bx.w * cy.w - by.w * cx.w));
    }

    acc0 += __shfl_down_sync(0xffffffffu, acc0, 16);
    acc1 += __shfl_down_sync(0xffffffffu, acc1, 16);
    acc2 += __shfl_down_sync(0xffffffffu, acc2, 16);
    acc3 += __shfl_down_sync(0xffffffffu, acc3, 16);
    if (lane < 16)
        ((float4*)sSum[wid])[bg] = make_float4(acc0, acc1, acc2, acc3);
    __syncthreads();

    if (threadIdx.x < 64) {
        float s = 0.f;
        #pragma unroll
        for (int w = 0; w < 8; w++) s += sSum[w][threadIdx.x];
        g_partial[blockIdx.x * 64 + threadIdx.x] = s;
    }
    __syncthreads();

    if (threadIdx.x == 0) {
        __threadfence();
        sTicket = atomicAdd(&g_counter, 1u);
    }
    __syncthreads();

    if (sTicket == DET_BLOCKS - 1) {
        __threadfence();
        {
            const int c = threadIdx.x & 63;
            const int q = threadIdx.x >> 6;
            const volatile float* p = g_partial;
            float s = 0.f;
            const int beg = q * (DET_BLOCKS / 4), end = beg + DET_BLOCKS / 4;
            for (int blk = beg; blk < end; blk++)
                s += p[blk * 64 + c];
            sQ[q][c] = s;
        }
        __syncthreads();
        if (threadIdx.x < 64) {
            float s = ((sQ[0][threadIdx.x] + sQ[1][threadIdx.x])
                     +  sQ[2][threadIdx.x]) + sQ[3][threadIdx.x];
            g_invscale[sigma6(threadIdx.x)] = 1.0f / cbrtf(s / 6.0f);
        }
        if (threadIdx.x == 0)
            g_counter = 0;
    }
}

// ---------------------------------------------------------------------------
// Output: read xTh (L2-hot), scale, inverse-transpose via conflict-free smem,
// write out[b][row] with coalesced float4 streaming stores.
// Half k of uint4 g = stored column 8g+k = REAL batch 8k+g. The smem tile is
// indexed by real batch, so the write phase needs no permutation.
// ---------------------------------------------------------------------------
__global__ void __launch_bounds__(512)
k_outT(float* __restrict__ out)
{
    __shared__ float tile_f[64 * 132];    // tile_f[real_batch*132 + r], 33 KB
    const int row0 = blockIdx.x * 128;

    // ---- read + scale: thread (g=tid&7, rr) loads uint4 g of row rr --------
    const int g   = threadIdx.x & 7;
    const int rr0 = threadIdx.x >> 3;                 // 0..63
    float finv[8];
    #pragma unroll
    for (int k = 0; k < 8; k++)
        finv[k] = g_invscale[8*k + g];                // real batch of half k

    #pragma unroll
    for (int p = 0; p < 2; p++) {
        const int rr  = rr0 + 64 * p;
        const int row = row0 + rr;
        if (row < ROWS) {
            uint4 u = *((const uint4*)(g_xTh + (size_t)row * 64) + g);
            const __half2* h2 = (const __half2*)&u;
            #pragma unroll
            for (int k2 = 0; k2 < 4; k2++) {
                float2 f = __half22float2(h2[k2]);
                // half index k=2k2(+1) -> real batch 8k+g; banks (4g+rr) mod 32
                tile_f[(8*(2*k2+0) + g) * 132 + rr] = f.x * finv[2*k2+0];
                tile_f[(8*(2*k2+1) + g) * 132 + rr] = f.y * finv[2*k2+1];
            }
        }
    }
    __syncthreads();

    // ---- write: item -> (batch b, row quad); LDS.128 + coalesced STG.128 ----
    #pragma unroll
    for (int j = 0; j < 4; j++) {
        const int item = j * 512 + threadIdx.x;       // 0..2047
        const int b    = item >> 5;                   // real batch 0..63
        const int quad = item & 31;                   // row quad within tile
        const int row  = row0 + 4 * quad;
        if (row < ROWS) {                             // ROWS%4==0: quad fully valid
            float4 v = *(const float4*)(tile_f + b * 132 + 4 * quad);
            __stcs((float4*)(out + (size_t)b * ROWS + row), v);
        }
    }
}

// ---------------------------------------------------------------------------
extern "C" void kernel_launch(void* const* d_in, const int* in_sizes, int n_in,
                              void* d_out, int out_size)
{
    // x: 19,200,000 float32 ; M: 600,000 int32 — select by element count.
    const float* x;
    const int*   M;
    if (in_sizes[0] == 19200000) { x = (const float*)d_in[0]; M = (const int*)d_in[1]; }
    else                         { x = (const float*)d_in[1]; M = (const int*)d_in[0]; }
    float* o = (float*)d_out;

    const int tBlocks = (ROWS + 127) / 128;    // 2344
    k_transpose<<<tBlocks, 512>>>(x);
    k_det<<<DET_BLOCKS, DET_THREADS>>>(M);
    k_outT<<<tBlocks, 512>>>(o);
}

// round 11
// speedup vs baseline: 1.2355x; 1.0304x over previous
#include <cuda_runtime.h>
#include <cuda_fp16.h>
#include <cuda_bf16.h>

#define N_VERTS 100000
#define N_TETS  200000
#define BATCH   64
#define ROWS    (3 * N_VERTS)      // 300000

#define DET_BLOCKS 1184            // 8 CTAs/SM on 148 SMs
#define DET_THREADS 256

// batch permutation inside g_xTh: column j holds real batch sigma(j);
// sigma(t) = ((t&7)<<3)|(t>>3), self-inverse.
__device__ __forceinline__ int sigma6(int t) { return ((t & 7) << 3) | (t >> 3); }

__device__ __half g_xTh[(size_t)ROWS * BATCH];        // 38.4 MB fp16 transposed x
__device__ float  g_partial[DET_BLOCKS * BATCH];
__device__ float  g_invscale[BATCH];                  // indexed by REAL batch
__device__ unsigned g_counter;                        // zero-init, self-resetting

// ---------------------------------------------------------------------------
// Transpose x[64][300000] -> xTh[300000][64] (fp16, batch-permuted by sigma).
// Fill uses vector __ldcs (LDG.E.128, evict-first: x is read exactly once in
// the pipeline, keep L2 for xTh). Drain: thread-octet g gathers smem columns
// {8k+g} into CONTIGUOUS halves 8g+k of the row => stored column j holds real
// batch sigma(j).
// ---------------------------------------------------------------------------
__global__ void __launch_bounds__(512)
k_transpose(const float* __restrict__ x)
{
    __shared__ float4 tile4[64][33];
    const float* tile_f = (const float*)tile4;        // tile_f[b*132 + r]
    const int row0 = blockIdx.x * 128;

    // ---- fill: warp w, iter j: batch b=16j+w, LDG.128 of rows 4tx..4tx+3 ----
    const int tx = threadIdx.x & 31;
    const int w  = threadIdx.x >> 5;                  // 0..15
    const int r4 = row0 + 4 * tx;
    if (r4 < ROWS) {                                  // ROWS%4==0 -> quad fully valid
        #pragma unroll
        for (int j = 0; j < 4; j++) {
            const int b = j * 16 + w;
            tile4[b][tx] = __ldcs((const float4*)(x + (size_t)b * ROWS + r4));
        }
    }
    __syncthreads();

    // ---- drain: thread (g, rr): 8 LDS (banks 4g+rr, distinct) -> STG.128 ----
    const int g   = threadIdx.x & 7;
    const int rr0 = threadIdx.x >> 3;                 // 0..63
    #pragma unroll
    for (int p = 0; p < 2; p++) {
        const int rr  = rr0 + 64 * p;
        const int row = row0 + rr;
        if (row < ROWS) {
            __half h[8];
            #pragma unroll
            for (int k = 0; k < 8; k++)
                h[k] = __float2half_rn(tile_f[(8*k + g) * 132 + rr]);
            ((uint4*)(g_xTh + (size_t)row * 64))[g] = *(const uint4*)h;
        }
    }
}

// ---------------------------------------------------------------------------
// fp16 row-group load: 4 columns (8 bytes) -> float4
// ---------------------------------------------------------------------------
__device__ __forceinline__ float4 ldh4(const __half* p)
{
    uint2 u = __ldg((const uint2*)p);
    float2 f0 = __half22float2(*(const __half2*)&u.x);
    float2 f1 = __half22float2(*(const __half2*)&u.y);
    return make_float4(f0.x, f0.y, f1.x, f1.y);
}

// ---------------------------------------------------------------------------
// Det kernel: each warp handles 2 tets x 64 columns per iteration.
// Last block (fenced atomic ticket) reduces partials -> g_invscale (un-permuted).
// ---------------------------------------------------------------------------
__global__ void __launch_bounds__(DET_THREADS)
k_det(const int* __restrict__ M)
{
    __shared__ float sSum[8][64];
    __shared__ float sQ[4][64];
    __shared__ unsigned sTicket;

    const int wid  = threadIdx.x >> 5;
    const int lane = threadIdx.x & 31;
    const int half = lane >> 4;
    const int bg   = lane & 15;

    float acc0 = 0.f, acc1 = 0.f, acc2 = 0.f, acc3 = 0.f;

    #pragma unroll 2
    for (int base = blockIdx.x * 16; base < N_TETS; base += DET_BLOCKS * 16) {
        const int t  = base + wid * 2 + half;
        const int i0 = __ldg(M + 3 * t + 0);
        const int i1 = __ldg(M + 3 * t + 1);
        const int i2 = __ldg(M + 3 * t + 2);

        const __half* pa = g_xTh + (size_t)(3 * i0) * 64 + bg * 4;
        const __half* pb = g_xTh + (size_t)(3 * i1) * 64 + bg * 4;
        const __half* pc = g_xTh + (size_t)(3 * i2) * 64 + bg * 4;

        float4 ax = ldh4(pa), ay = ldh4(pa + 64), az = ldh4(pa + 128);
        float4 bx = ldh4(pb), by = ldh4(pb + 64), bz = ldh4(pb + 128);
        float4 cx = ldh4(pc), cy = ldh4(pc + 64), cz = ldh4(pc + 128);

        acc0 += fabsf(ax.x * (by.x * cz.x - bz.x * cy.x)
                    - ay.x * (bx.x * cz.x - bz.x * cx.x)
                    + az.x * (bx.x * cy.x - by.x * cx.x));
        acc1 += fabsf(ax.y * (by.y * cz.y - bz.y * cy.y)
                    - ay.y * (bx.y * cz.y - bz.y * cx.y)
                    + az.y * (bx.y * cy.y - by.y * cx.y));
        acc2 += fabsf(ax.z * (by.z * cz.z - bz.z * cy.z)
                    - ay.z * (bx.z * cz.z - bz.z * cx.z)
                    + az.z * (bx.z * cy.z - by.z * cx.z));
        acc3 += fabsf(ax.w * (by.w * cz.w - bz.w * cy.w)
                    - ay.w * (bx.w * cz.w - bz.w * cx.w)
                    + az.w * (bx.w * cy.w - by.w * cx.w));
    }

    acc0 += __shfl_down_sync(0xffffffffu, acc0, 16);
    acc1 += __shfl_down_sync(0xffffffffu, acc1, 16);
    acc2 += __shfl_down_sync(0xffffffffu, acc2, 16);
    acc3 += __shfl_down_sync(0xffffffffu, acc3, 16);
    if (lane < 16)
        ((float4*)sSum[wid])[bg] = make_float4(acc0, acc1, acc2, acc3);
    __syncthreads();

    if (threadIdx.x < 64) {
        float s = 0.f;
        #pragma unroll
        for (int w = 0; w < 8; w++) s += sSum[w][threadIdx.x];
        g_partial[blockIdx.x * 64 + threadIdx.x] = s;
    }
    __syncthreads();

    if (threadIdx.x == 0) {
        __threadfence();
        sTicket = atomicAdd(&g_counter, 1u);
    }
    __syncthreads();

    if (sTicket == DET_BLOCKS - 1) {
        __threadfence();
        {
            const int c = threadIdx.x & 63;
            const int q = threadIdx.x >> 6;
            const volatile float* p = g_partial;
            float s = 0.f;
            const int beg = q * (DET_BLOCKS / 4), end = beg + DET_BLOCKS / 4;
            for (int blk = beg; blk < end; blk++)
                s += p[blk * 64 + c];
            sQ[q][c] = s;
        }
        __syncthreads();
        if (threadIdx.x < 64) {
            float s = ((sQ[0][threadIdx.x] + sQ[1][threadIdx.x])
                     +  sQ[2][threadIdx.x]) + sQ[3][threadIdx.x];
            g_invscale[sigma6(threadIdx.x)] = 1.0f / cbrtf(s / 6.0f);
        }
        if (threadIdx.x == 0)
            g_counter = 0;
    }
}

// ---------------------------------------------------------------------------
// Output: read xTh (L2-hot), scale, inverse-transpose via conflict-free smem,
// write out[b][row] with coalesced float4 streaming stores.
// Half k of uint4 g = stored column 8g+k = REAL batch 8k+g; smem tile indexed
// by real batch so the write phase needs no permutation.
// ---------------------------------------------------------------------------
__global__ void __launch_bounds__(512)
k_outT(float* __restrict__ out)
{
    __shared__ float tile_f[64 * 132];    // tile_f[real_batch*132 + r], 33 KB
    const int row0 = blockIdx.x * 128;

    // ---- read + scale: thread (g=tid&7, rr) loads uint4 g of row rr --------
    const int g   = threadIdx.x & 7;
    const int rr0 = threadIdx.x >> 3;                 // 0..63
    float finv[8];
    #pragma unroll
    for (int k = 0; k < 8; k++)
        finv[k] = g_invscale[8*k + g];                // real batch of half k

    #pragma unroll
    for (int p = 0; p < 2; p++) {
        const int rr  = rr0 + 64 * p;
        const int row = row0 + rr;
        if (row < ROWS) {
            uint4 u = *((const uint4*)(g_xTh + (size_t)row * 64) + g);
            const __half2* h2 = (const __half2*)&u;
            #pragma unroll
            for (int k2 = 0; k2 < 4; k2++) {
                float2 f = __half22float2(h2[k2]);
                tile_f[(8*(2*k2+0) + g) * 132 + rr] = f.x * finv[2*k2+0];
                tile_f[(8*(2*k2+1) + g) * 132 + rr] = f.y * finv[2*k2+1];
            }
        }
    }
    __syncthreads();

    // ---- write: item -> (batch b, row quad); LDS.128 + coalesced STG.128 ----
    #pragma unroll
    for (int j = 0; j < 4; j++) {
        const int item = j * 512 + threadIdx.x;       // 0..2047
        const int b    = item >> 5;                   // real batch 0..63
        const int quad = item & 31;                   // row quad within tile
        const int row  = row0 + 4 * quad;
        if (row < ROWS) {                             // ROWS%4==0: quad fully valid
            float4 v = *(const float4*)(tile_f + b * 132 + 4 * quad);
            __stcs((float4*)(out + (size_t)b * ROWS + row), v);
        }
    }
}

// ---------------------------------------------------------------------------
extern "C" void kernel_launch(void* const* d_in, const int* in_sizes, int n_in,
                              void* d_out, int out_size)
{
    // x: 19,200,000 float32 ; M: 600,000 int32 — select by element count.
    const float* x;
    const int*   M;
    if (in_sizes[0] == 19200000) { x = (const float*)d_in[0]; M = (const int*)d_in[1]; }
    else                         { x = (const float*)d_in[1]; M = (const int*)d_in[0]; }
    float* o = (float*)d_out;

    const int tBlocks = (ROWS + 127) / 128;    // 2344
    k_transpose<<<tBlocks, 512>>>(x);
    k_det<<<DET_BLOCKS, DET_THREADS>>>(M);
    k_outT<<<tBlocks, 512>>>(o);
}

// round 12
// speedup vs baseline: 1.2388x; 1.0027x over previous
#include <cuda_runtime.h>
#include <cuda_fp16.h>
#include <cuda_bf16.h>

#define N_VERTS 100000
#define N_TETS  200000
#define BATCH   64
#define ROWS    (3 * N_VERTS)      // 300000

#define DET_BLOCKS 1184            // 8 CTAs/SM on 148 SMs
#define DET_THREADS 256
#define DET_STEP   (DET_BLOCKS * 16)

// batch permutation inside g_xTh: column j holds real batch sigma(j);
// sigma(t) = ((t&7)<<3)|(t>>3), self-inverse.
__device__ __forceinline__ int sigma6(int t) { return ((t & 7) << 3) | (t >> 3); }

__device__ __half g_xTh[(size_t)ROWS * BATCH];        // 38.4 MB fp16 transposed x
__device__ float  g_partial[DET_BLOCKS * BATCH];
__device__ float  g_invscale[BATCH];                  // indexed by REAL batch
__device__ unsigned g_counter;                        // zero-init, self-resetting

// ---------------------------------------------------------------------------
// Transpose x[64][300000] -> xTh[300000][64] (fp16, batch-permuted by sigma).
// ---------------------------------------------------------------------------
__global__ void __launch_bounds__(512)
k_transpose(const float* __restrict__ x)
{
    __shared__ float4 tile4[64][33];
    const float* tile_f = (const float*)tile4;        // tile_f[b*132 + r]
    const int row0 = blockIdx.x * 128;

    // ---- fill: warp w, iter j: batch b=16j+w, LDG.128 of rows 4tx..4tx+3 ----
    const int tx = threadIdx.x & 31;
    const int w  = threadIdx.x >> 5;                  // 0..15
    const int r4 = row0 + 4 * tx;
    if (r4 < ROWS) {                                  // ROWS%4==0 -> quad fully valid
        #pragma unroll
        for (int j = 0; j < 4; j++) {
            const int b = j * 16 + w;
            tile4[b][tx] = __ldcs((const float4*)(x + (size_t)b * ROWS + r4));
        }
    }
    __syncthreads();

    // ---- drain: thread (g, rr): 8 LDS (banks 4g+rr, distinct) -> STG.128 ----
    const int g   = threadIdx.x & 7;
    const int rr0 = threadIdx.x >> 3;                 // 0..63
    #pragma unroll
    for (int p = 0; p < 2; p++) {
        const int rr  = rr0 + 64 * p;
        const int row = row0 + rr;
        if (row < ROWS) {
            __half h[8];
            #pragma unroll
            for (int k = 0; k < 8; k++)
                h[k] = __float2half_rn(tile_f[(8*k + g) * 132 + rr]);
            ((uint4*)(g_xTh + (size_t)row * 64))[g] = *(const uint4*)h;
        }
    }
}

// ---------------------------------------------------------------------------
// uint2 (4 fp16) -> float4
// ---------------------------------------------------------------------------
__device__ __forceinline__ float4 h4f(uint2 u)
{
    float2 f0 = __half22float2(*(const __half2*)&u.x);
    float2 f1 = __half22float2(*(const __half2*)&u.y);
    return make_float4(f0.x, f0.y, f1.x, f1.y);
}

// ---------------------------------------------------------------------------
// Det kernel with software-pipelined index loads: the next iteration's 3 M
// indices are fetched while this iteration's 9 gathers are in flight, so the
// dependent chain per iteration is ~one L2 latency, not two.
// ---------------------------------------------------------------------------
__global__ void __launch_bounds__(DET_THREADS)
k_det(const int* __restrict__ M)
{
    __shared__ float sSum[8][64];
    __shared__ float sQ[4][64];
    __shared__ unsigned sTicket;

    const int wid  = threadIdx.x >> 5;
    const int lane = threadIdx.x & 31;
    const int half = lane >> 4;
    const int bg   = lane & 15;

    float acc0 = 0.f, acc1 = 0.f, acc2 = 0.f, acc3 = 0.f;

    int t = blockIdx.x * 16 + wid * 2 + half;         // < DET_STEP <= N_TETS
    int i0 = __ldg(M + 3 * t + 0);
    int i1 = __ldg(M + 3 * t + 1);
    int i2 = __ldg(M + 3 * t + 2);

    while (t < N_TETS) {
        // prefetch next iteration's indices (clamped; unused on last trip)
        const int tn = min(t + DET_STEP, N_TETS - 1);
        const int j0 = __ldg(M + 3 * tn + 0);
        const int j1 = __ldg(M + 3 * tn + 1);
        const int j2 = __ldg(M + 3 * tn + 2);

        const uint2* pa = (const uint2*)(g_xTh + (size_t)(3 * i0) * 64) + bg;
        const uint2* pb = (const uint2*)(g_xTh + (size_t)(3 * i1) * 64) + bg;
        const uint2* pc = (const uint2*)(g_xTh + (size_t)(3 * i2) * 64) + bg;

        // 9 independent LDG.64 — raw loads first so they batch
        uint2 ua0 = __ldg(pa), ua1 = __ldg(pa + 16), ua2 = __ldg(pa + 32);
        uint2 ub0 = __ldg(pb), ub1 = __ldg(pb + 16), ub2 = __ldg(pb + 32);
        uint2 uc0 = __ldg(pc), uc1 = __ldg(pc + 16), uc2 = __ldg(pc + 32);

        float4 ax = h4f(ua0), ay = h4f(ua1), az = h4f(ua2);
        float4 bx = h4f(ub0), by = h4f(ub1), bz = h4f(ub2);
        float4 cx = h4f(uc0), cy = h4f(uc1), cz = h4f(uc2);

        acc0 += fabsf(ax.x * (by.x * cz.x - bz.x * cy.x)
                    - ay.x * (bx.x * cz.x - bz.x * cx.x)
                    + az.x * (bx.x * cy.x - by.x * cx.x));
        acc1 += fabsf(ax.y * (by.y * cz.y - bz.y * cy.y)
                    - ay.y * (bx.y * cz.y - bz.y * cx.y)
                    + az.y * (bx.y * cy.y - by.y * cx.y));
        acc2 += fabsf(ax.z * (by.z * cz.z - bz.z * cy.z)
                    - ay.z * (bx.z * cz.z - bz.z * cx.z)
                    + az.z * (bx.z * cy.z - by.z * cx.z));
        acc3 += fabsf(ax.w * (by.w * cz.w - bz.w * cy.w)
                    - ay.w * (bx.w * cz.w - bz.w * cx.w)
                    + az.w * (bx.w * cy.w - by.w * cx.w));

        i0 = j0; i1 = j1; i2 = j2;
        t += DET_STEP;
    }

    acc0 += __shfl_down_sync(0xffffffffu, acc0, 16);
    acc1 += __shfl_down_sync(0xffffffffu, acc1, 16);
    acc2 += __shfl_down_sync(0xffffffffu, acc2, 16);
    acc3 += __shfl_down_sync(0xffffffffu, acc3, 16);
    if (lane < 16)
        ((float4*)sSum[wid])[bg] = make_float4(acc0, acc1, acc2, acc3);
    __syncthreads();

    if (threadIdx.x < 64) {
        float s = 0.f;
        #pragma unroll
        for (int w = 0; w < 8; w++) s += sSum[w][threadIdx.x];
        g_partial[blockIdx.x * 64 + threadIdx.x] = s;
    }
    __syncthreads();

    if (threadIdx.x == 0) {
        __threadfence();
        sTicket = atomicAdd(&g_counter, 1u);
    }
    __syncthreads();

    if (sTicket == DET_BLOCKS - 1) {
        __threadfence();
        {
            const int c = threadIdx.x & 63;
            const int q = threadIdx.x >> 6;
            const volatile float* p = g_partial;
            float s = 0.f;
            const int beg = q * (DET_BLOCKS / 4), end = beg + DET_BLOCKS / 4;
            for (int blk = beg; blk < end; blk++)
                s += p[blk * 64 + c];
            sQ[q][c] = s;
        }
        __syncthreads();
        if (threadIdx.x < 64) {
            float s = ((sQ[0][threadIdx.x] + sQ[1][threadIdx.x])
                     +  sQ[2][threadIdx.x]) + sQ[3][threadIdx.x];
            g_invscale[sigma6(threadIdx.x)] = 1.0f / cbrtf(s / 6.0f);
        }
        if (threadIdx.x == 0)
            g_counter = 0;
    }
}

// ---------------------------------------------------------------------------
// Output: read xTh (L2-hot), scale, inverse-transpose via conflict-free smem,
// write out[b][row] with coalesced float4 streaming stores.
// ---------------------------------------------------------------------------
__global__ void __launch_bounds__(512)
k_outT(float* __restrict__ out)
{
    __shared__ float tile_f[64 * 132];    // tile_f[real_batch*132 + r], 33 KB
    const int row0 = blockIdx.x * 128;

    const int g   = threadIdx.x & 7;
    const int rr0 = threadIdx.x >> 3;                 // 0..63
    float finv[8];
    #pragma unroll
    for (int k = 0; k < 8; k++)
        finv[k] = g_invscale[8*k + g];                // real batch of half k

    #pragma unroll
    for (int p = 0; p < 2; p++) {
        const int rr  = rr0 + 64 * p;
        const int row = row0 + rr;
        if (row < ROWS) {
            uint4 u = *((const uint4*)(g_xTh + (size_t)row * 64) + g);
            const __half2* h2 = (const __half2*)&u;
            #pragma unroll
            for (int k2 = 0; k2 < 4; k2++) {
                float2 f = __half22float2(h2[k2]);
                tile_f[(8*(2*k2+0) + g) * 132 + rr] = f.x * finv[2*k2+0];
                tile_f[(8*(2*k2+1) + g) * 132 + rr] = f.y * finv[2*k2+1];
            }
        }
    }
    __syncthreads();

    #pragma unroll
    for (int j = 0; j < 4; j++) {
        const int item = j * 512 + threadIdx.x;       // 0..2047
        const int b    = item >> 5;                   // real batch 0..63
        const int quad = item & 31;                   // row quad within tile
        const int row  = row0 + 4 * quad;
        if (row < ROWS) {
            float4 v = *(const float4*)(tile_f + b * 132 + 4 * quad);
            __stcs((float4*)(out + (size_t)b * ROWS + row), v);
        }
    }
}

// ---------------------------------------------------------------------------
extern "C" void kernel_launch(void* const* d_in, const int* in_sizes, int n_in,
                              void* d_out, int out_size)
{
    // x: 19,200,000 float32 ; M: 600,000 int32 — select by element count.
    const float* x;
    const int*   M;
    if (in_sizes[0] == 19200000) { x = (const float*)d_in[0]; M = (const int*)d_in[1]; }
    else                         { x = (const float*)d_in[1]; M = (const int*)d_in[0]; }
    float* o = (float*)d_out;

    const int tBlocks = (ROWS + 127) / 128;    // 2344
    k_transpose<<<tBlocks, 512>>>(x);
    k_det<<<DET_BLOCKS, DET_THREADS>>>(M);
    k_outT<<<tBlocks, 512>>>(o);
}